// round 1
// baseline (speedup 1.0000x reference)
#include <cuda_runtime.h>
#include <math.h>

#define BATCH 4
#define SEQ   2048
#define DIM   1024

// Scratch: device globals (runtime allocation is forbidden).
__device__ float g_q[(size_t)BATCH * SEQ * DIM];                 // 32 MiB
__device__ float g_k[(size_t)BATCH * SEQ * DIM];                 // 32 MiB
__device__ float g_v[(size_t)BATCH * SEQ * DIM];                 // 32 MiB
__device__ float g_p[(size_t)BATCH * SEQ * SEQ];                 // 64 MiB

#define BM 128
#define BN 128
#define BK 16

// ---------------------------------------------------------------------------
// NT GEMM: C[m,n] = scale * sum_k A[m,k] * B[n,k]   (both operands K-major)
// Used for: projections (y = x @ W.T) and scores (Q @ K.T).
// causal=1: skip tiles strictly above the diagonal (bx > by).
// ---------------------------------------------------------------------------
__global__ __launch_bounds__(256)
void gemm_nt(const float* __restrict__ A, const float* __restrict__ B,
             float* __restrict__ C, int K, int ldc, float scale,
             long strideA, long strideB, long strideC, int causal)
{
    const int bx = blockIdx.x, by = blockIdx.y, bz = blockIdx.z;
    if (causal && bx > by) return;
    A += (long)bz * strideA;
    B += (long)bz * strideB;
    C += (long)bz * strideC;
    const int m0 = by * BM, n0 = bx * BN;

    __shared__ __align__(16) float sA[BK][BM + 4];
    __shared__ __align__(16) float sB[BK][BN + 4];

    const int tid = threadIdx.x;
    const int tx = tid & 15, ty = tid >> 4;

    float acc[8][8];
    #pragma unroll
    for (int i = 0; i < 8; i++)
        #pragma unroll
        for (int j = 0; j < 8; j++) acc[i][j] = 0.f;

    for (int k0 = 0; k0 < K; k0 += BK) {
        #pragma unroll
        for (int l = 0; l < 2; ++l) {
            const int idx4 = tid + l * 256;       // 512 float4s cover a 128x16 tile
            const int row  = idx4 >> 2;
            const int cv   = (idx4 & 3) << 2;
            const float4 va = *(const float4*)(A + (long)(m0 + row) * K + k0 + cv);
            sA[cv + 0][row] = va.x; sA[cv + 1][row] = va.y;
            sA[cv + 2][row] = va.z; sA[cv + 3][row] = va.w;
            const float4 vb = *(const float4*)(B + (long)(n0 + row) * K + k0 + cv);
            sB[cv + 0][row] = vb.x; sB[cv + 1][row] = vb.y;
            sB[cv + 2][row] = vb.z; sB[cv + 3][row] = vb.w;
        }
        __syncthreads();
        #pragma unroll
        for (int k = 0; k < BK; k++) {
            float a[8], b[8];
            *(float4*)&a[0] = *(const float4*)&sA[k][ty * 8];
            *(float4*)&a[4] = *(const float4*)&sA[k][ty * 8 + 4];
            *(float4*)&b[0] = *(const float4*)&sB[k][tx * 8];
            *(float4*)&b[4] = *(const float4*)&sB[k][tx * 8 + 4];
            #pragma unroll
            for (int i = 0; i < 8; i++)
                #pragma unroll
                for (int j = 0; j < 8; j++)
                    acc[i][j] = fmaf(a[i], b[j], acc[i][j]);
        }
        __syncthreads();
    }

    #pragma unroll
    for (int i = 0; i < 8; i++) {
        const long off = (long)(m0 + ty * 8 + i) * ldc + n0 + tx * 8;
        float4 o0, o1;
        o0.x = acc[i][0] * scale; o0.y = acc[i][1] * scale;
        o0.z = acc[i][2] * scale; o0.w = acc[i][3] * scale;
        o1.x = acc[i][4] * scale; o1.y = acc[i][5] * scale;
        o1.z = acc[i][6] * scale; o1.w = acc[i][7] * scale;
        *(float4*)(C + off)     = o0;
        *(float4*)(C + off + 4) = o1;
    }
}

// ---------------------------------------------------------------------------
// Row-wise causal softmax over g_p. One CTA per row (N*S rows, T=2048 cols).
// Writes probabilities for t<=s and EXACT ZEROS for t>s (so PV can do a
// plain GEMM with a per-tile k bound).
// ---------------------------------------------------------------------------
__global__ __launch_bounds__(256)
void softmax_causal(float* __restrict__ P)
{
    const int r = blockIdx.x;              // row id in [0, BATCH*SEQ)
    const int s = r & (SEQ - 1);           // query position (causal bound)
    float* row = P + (long)r * SEQ;
    const int tid = threadIdx.x;

    float x[8];
    float m = -INFINITY;
    #pragma unroll
    for (int i = 0; i < 8; i++) {
        const int t = tid + i * 256;
        x[i] = (t <= s) ? row[t] : -INFINITY;
        m = fmaxf(m, x[i]);
    }

    __shared__ float red[256];
    red[tid] = m; __syncthreads();
    #pragma unroll
    for (int off = 128; off > 0; off >>= 1) {
        if (tid < off) red[tid] = fmaxf(red[tid], red[tid + off]);
        __syncthreads();
    }
    m = red[0];
    __syncthreads();

    float e[8];
    float sum = 0.f;
    #pragma unroll
    for (int i = 0; i < 8; i++) {
        const int t = tid + i * 256;
        e[i] = (t <= s) ? expf(x[i] - m) : 0.f;
        sum += e[i];
    }
    red[tid] = sum; __syncthreads();
    #pragma unroll
    for (int off = 128; off > 0; off >>= 1) {
        if (tid < off) red[tid] += red[tid + off];
        __syncthreads();
    }
    const float inv = 1.f / red[0];

    #pragma unroll
    for (int i = 0; i < 8; i++)
        row[tid + i * 256] = e[i] * inv;
}

// ---------------------------------------------------------------------------
// NN GEMM for PV: C[s,e] = sum_t P[s,t] * V[t,e], per batch.
// Causal: P is exactly zero for t > s, so the k-loop stops at the end of the
// diagonal tile (kmax = m0 + BM) — halves the work and never reads junk.
// ---------------------------------------------------------------------------
__global__ __launch_bounds__(256)
void gemm_nn_pv(const float* __restrict__ Pbase, const float* __restrict__ Vbase,
                float* __restrict__ Cbase)
{
    const int bz = blockIdx.z;
    const float* A = Pbase + (long)bz * SEQ * SEQ;   // [SEQ x SEQ], k-major
    const float* B = Vbase + (long)bz * SEQ * DIM;   // [SEQ x DIM], n-major
    float* C       = Cbase + (long)bz * SEQ * DIM;
    const int m0 = blockIdx.y * BM, n0 = blockIdx.x * BN;
    const int kmax = m0 + BM;                        // causal bound (<= SEQ)

    __shared__ __align__(16) float sA[BK][BM + 4];
    __shared__ __align__(16) float sB[BK][BN + 4];

    const int tid = threadIdx.x;
    const int tx = tid & 15, ty = tid >> 4;

    float acc[8][8];
    #pragma unroll
    for (int i = 0; i < 8; i++)
        #pragma unroll
        for (int j = 0; j < 8; j++) acc[i][j] = 0.f;

    for (int k0 = 0; k0 < kmax; k0 += BK) {
        #pragma unroll
        for (int l = 0; l < 2; ++l) {
            const int idx4 = tid + l * 256;
            {   // A tile: 128 rows x 16 k-cols, transposed into sA
                const int row = idx4 >> 2;
                const int cv  = (idx4 & 3) << 2;
                const float4 va = *(const float4*)(A + (long)(m0 + row) * SEQ + k0 + cv);
                sA[cv + 0][row] = va.x; sA[cv + 1][row] = va.y;
                sA[cv + 2][row] = va.z; sA[cv + 3][row] = va.w;
            }
            {   // B tile: 16 k-rows x 128 n-cols, direct (coalesced along n)
                const int kk = idx4 >> 5;
                const int cv = (idx4 & 31) << 2;
                *(float4*)&sB[kk][cv] =
                    *(const float4*)(B + (long)(k0 + kk) * DIM + n0 + cv);
            }
        }
        __syncthreads();
        #pragma unroll
        for (int k = 0; k < BK; k++) {
            float a[8], b[8];
            *(float4*)&a[0] = *(const float4*)&sA[k][ty * 8];
            *(float4*)&a[4] = *(const float4*)&sA[k][ty * 8 + 4];
            *(float4*)&b[0] = *(const float4*)&sB[k][tx * 8];
            *(float4*)&b[4] = *(const float4*)&sB[k][tx * 8 + 4];
            #pragma unroll
            for (int i = 0; i < 8; i++)
                #pragma unroll
                for (int j = 0; j < 8; j++)
                    acc[i][j] = fmaf(a[i], b[j], acc[i][j]);
        }
        __syncthreads();
    }

    #pragma unroll
    for (int i = 0; i < 8; i++) {
        const long off = (long)(m0 + ty * 8 + i) * DIM + n0 + tx * 8;
        *(float4*)(C + off)     = *(float4*)&acc[i][0];
        *(float4*)(C + off + 4) = *(float4*)&acc[i][4];
    }
}

// ---------------------------------------------------------------------------
// Launch: q/k/v projections -> causal QK^T -> softmax -> PV
// Inputs (metadata order): query, key, value, attn_mask, Wq, Wk, Wv
// ---------------------------------------------------------------------------
extern "C" void kernel_launch(void* const* d_in, const int* in_sizes, int n_in,
                              void* d_out, int out_size)
{
    const float* query = (const float*)d_in[0];
    const float* key   = (const float*)d_in[1];
    const float* value = (const float*)d_in[2];
    // d_in[3] = attn_mask (causal tril, applied analytically by index)
    const float* Wq    = (const float*)d_in[4];
    const float* Wk    = (const float*)d_in[5];
    const float* Wv    = (const float*)d_in[6];
    float* out = (float*)d_out;

    float *qb, *kb, *vb, *pb;
    cudaGetSymbolAddress((void**)&qb, g_q);
    cudaGetSymbolAddress((void**)&kb, g_k);
    cudaGetSymbolAddress((void**)&vb, g_v);
    cudaGetSymbolAddress((void**)&pb, g_p);

    const dim3 blk(256);

    // Projections: [BATCH*SEQ, DIM] = X @ W.T
    const dim3 gproj(DIM / BN, (BATCH * SEQ) / BM, 1);
    gemm_nt<<<gproj, blk>>>(query, Wq, qb, DIM, DIM, 1.f, 0, 0, 0, 0);
    gemm_nt<<<gproj, blk>>>(key,   Wk, kb, DIM, DIM, 1.f, 0, 0, 0, 0);
    gemm_nt<<<gproj, blk>>>(value, Wv, vb, DIM, DIM, 1.f, 0, 0, 0, 0);

    // Scores: P = (Q @ K.T) / sqrt(D), lower-triangle tiles only
    const dim3 gqk(SEQ / BN, SEQ / BM, BATCH);
    gemm_nt<<<gqk, blk>>>(qb, kb, pb, DIM, SEQ, 0.03125f,
                          (long)SEQ * DIM, (long)SEQ * DIM, (long)SEQ * SEQ, 1);

    // Causal softmax (writes zeros above the diagonal)
    softmax_causal<<<BATCH * SEQ, 256>>>(pb);

    // Output: Y = P @ V
    const dim3 gpv(DIM / BN, SEQ / BM, BATCH);
    gemm_nn_pv<<<gpv, blk>>>(pb, vb, out);
}

// round 3
// speedup vs baseline: 2.4550x; 2.4550x over previous
#include <cuda_runtime.h>
#include <cuda_bf16.h>
#include <stdint.h>
#include <math.h>

#define BATCH 4
#define SEQ   2048
#define DIM   1024
#define NSD   ((size_t)BATCH * SEQ * DIM)   // 8388608
#define NSS   ((size_t)BATCH * SEQ * SEQ)   // 16777216
#define DD    ((size_t)DIM * DIM)           // 1048576

typedef __nv_bfloat16 bf16;

// ---------------------------------------------------------------------------
// Scratch (device globals; runtime allocation is forbidden)
// ---------------------------------------------------------------------------
__device__ bf16 g_aqh[NSD], g_aql[NSD];     // split(query input)
__device__ bf16 g_akh[NSD], g_akl[NSD];     // split(key input)
__device__ bf16 g_avh[NSD], g_avl[NSD];     // split(value input)
__device__ bf16 g_wqh[DD],  g_wql[DD];
__device__ bf16 g_wkh[DD],  g_wkl[DD];
__device__ bf16 g_wvh[DD],  g_wvl[DD];
__device__ bf16 g_qh[NSD],  g_ql[NSD];      // projected q, split
__device__ bf16 g_kh[NSD],  g_kl[NSD];      // projected k, split
__device__ float g_v[NSD];                  // projected v, fp32
__device__ bf16 g_vth[NSD], g_vtl[NSD];     // v transposed [B][D][T], split
__device__ float g_p[NSS];                  // scores fp32
__device__ bf16 g_ph[NSS],  g_pl[NSS];      // softmax probs, split

// ---------------------------------------------------------------------------
// Helpers
// ---------------------------------------------------------------------------
__device__ __forceinline__ uint32_t smem_u32(const void* p) {
    uint32_t a;
    asm("{ .reg .u64 t; cvta.to.shared.u64 t, %1; cvt.u32.u64 %0, t; }" : "=r"(a) : "l"(p));
    return a;
}

__device__ __forceinline__ void split1(float x, bf16& h, bf16& l) {
    h = __float2bfloat16(x);
    l = __float2bfloat16(x - __bfloat162float(h));
}
__device__ __forceinline__ uint32_t pack2(bf16 a, bf16 b) {
    __nv_bfloat162 t; t.x = a; t.y = b;
    return *(uint32_t*)&t;
}

#define LDSM_X4(r, addr) \
    asm volatile("ldmatrix.sync.aligned.m8n8.x4.shared.b16 {%0,%1,%2,%3}, [%4];" \
        : "=r"((r)[0]), "=r"((r)[1]), "=r"((r)[2]), "=r"((r)[3]) : "r"(addr))

#define MMA_BF16(acc, a, b0, b1) \
    asm volatile("mma.sync.aligned.m16n8k16.row.col.f32.bf16.bf16.f32 " \
        "{%0,%1,%2,%3}, {%4,%5,%6,%7}, {%8,%9}, {%0,%1,%2,%3};" \
        : "+f"((acc)[0]), "+f"((acc)[1]), "+f"((acc)[2]), "+f"((acc)[3]) \
        : "r"((a)[0]), "r"((a)[1]), "r"((a)[2]), "r"((a)[3]), "r"(b0), "r"(b1))

#define CP_ASYNC16(s, g) \
    asm volatile("cp.async.cg.shared.global [%0], [%1], 16;" :: "r"(s), "l"(g))
#define CP_COMMIT() asm volatile("cp.async.commit_group;" ::: "memory")
#define CP_WAIT2()  asm volatile("cp.async.wait_group 2;" ::: "memory")

// smem tile: 128 rows x 32 bf16 cols = 64B/row; XOR swizzle of 16B chunks so
// ldmatrix phases (8 rows, fixed chunk) hit 8 distinct 16B bank-groups.
__device__ __forceinline__ uint32_t swz64(uint32_t row, uint32_t chunk) {
    return row * 64u + ((chunk ^ ((row >> 1) & 3u)) << 4);
}

// ---------------------------------------------------------------------------
// Elementwise split: fp32 -> (hi, lo) bf16
// ---------------------------------------------------------------------------
__global__ __launch_bounds__(256)
void split4_kernel(const float4* __restrict__ x, uint2* __restrict__ hi,
                   uint2* __restrict__ lo, int n4)
{
    int i = blockIdx.x * 256 + threadIdx.x;
    if (i >= n4) return;
    float4 v = x[i];
    bf16 h0, h1, h2, h3, l0, l1, l2, l3;
    split1(v.x, h0, l0); split1(v.y, h1, l1);
    split1(v.z, h2, l2); split1(v.w, h3, l3);
    uint2 H; H.x = pack2(h0, h1); H.y = pack2(h2, h3);
    uint2 L; L.x = pack2(l0, l1); L.y = pack2(l2, l3);
    hi[i] = H; lo[i] = L;
}

// ---------------------------------------------------------------------------
// Transpose + split: v[b][t][d] fp32 -> vt_hi/lo[b][d][t] bf16
// ---------------------------------------------------------------------------
__global__ __launch_bounds__(256)
void transpose_split_kernel(const float* __restrict__ v, bf16* __restrict__ th,
                            bf16* __restrict__ tl)
{
    __shared__ float tile[32][33];
    const int b = blockIdx.z;
    const int t0 = blockIdx.y * 32, d0 = blockIdx.x * 32;
    const int tx = threadIdx.x & 31, ty = threadIdx.x >> 5;   // 32 x 8
    const float* vb = v + (size_t)b * SEQ * DIM;
    #pragma unroll
    for (int i = 0; i < 4; i++)
        tile[ty + i * 8][tx] = vb[(size_t)(t0 + ty + i * 8) * DIM + d0 + tx];
    __syncthreads();
    bf16* thb = th + (size_t)b * DIM * SEQ;
    bf16* tlb = tl + (size_t)b * DIM * SEQ;
    #pragma unroll
    for (int i = 0; i < 4; i++) {
        float x = tile[tx][ty + i * 8];
        bf16 h, l; split1(x, h, l);
        const size_t o = (size_t)(d0 + ty + i * 8) * SEQ + t0 + tx;
        thb[o] = h; tlb[o] = l;
    }
}

// ---------------------------------------------------------------------------
// bf16x3-emulated NT GEMM on mma.sync (HMMA).
// C[m,n] = scale * sum_k A[m,k]*B[n,k], A=Ah+Al, B=Bh+Bl.
// CTA tile 128x128, k-chunk 32, 8 warps (warp tile 64x32), 4-stage cp.async.
// causal: skip tiles bx>by. pvlim: bound k at m0+128. split_out: bf16 hi/lo C.
// ---------------------------------------------------------------------------
#define TILE_B   8192                  // one 128x32 bf16 tile
#define STAGE_B  (4 * TILE_B)          // Ah, Al, Bh, Bl
#define NSTAGE   4
#define G_SMEM   (NSTAGE * STAGE_B)    // 128 KiB

__global__ __launch_bounds__(256)
void gemm_mma(const bf16* __restrict__ Ah, const bf16* __restrict__ Al, long sA,
              const bf16* __restrict__ Bh, const bf16* __restrict__ Bl, long sB,
              float* __restrict__ Cf, bf16* __restrict__ Chi, bf16* __restrict__ Clo,
              long sC, int K, int ldc, float scale, int causal, int pvlim, int split_out)
{
    const int bx = blockIdx.x, by = blockIdx.y, bz = blockIdx.z;
    if (causal && bx > by) return;
    const int m0 = by * 128, n0 = bx * 128;
    Ah += (long)bz * sA; Al += (long)bz * sA;
    Bh += (long)bz * sB; Bl += (long)bz * sB;

    extern __shared__ __align__(128) char smem[];
    const uint32_t sb = smem_u32(smem);

    const int tid  = threadIdx.x;
    const int lane = tid & 31, wid = tid >> 5;
    const int wm = (wid & 1) * 64;          // warp row offset in tile
    const int wn = (wid >> 1) * 32;         // warp col offset in tile

    const int klim = pvlim ? (m0 + 128) : K;
    const int nch  = klim >> 5;             // chunks of 32

    // issue loads of one chunk (4 tiles) into a stage
    auto load_chunk = [&](int c, int stage) {
        const int k0 = c << 5;
        const uint32_t st = sb + stage * STAGE_B;
        #pragma unroll
        for (int i = 0; i < 2; i++) {
            const int id = tid + (i << 8);      // 0..511 chunk ids per tile
            const int row = id >> 2, cc = id & 3;
            const uint32_t so = swz64(row, cc);
            const long go = (long)row * K + k0 + cc * 8;
            CP_ASYNC16(st + 0 * TILE_B + so, Ah + (long)(m0 + row) * K - (long)row * K + go);
            CP_ASYNC16(st + 1 * TILE_B + so, Al + (long)(m0 + row) * K - (long)row * K + go);
            CP_ASYNC16(st + 2 * TILE_B + so, Bh + (long)(n0 + row) * K - (long)row * K + go);
            CP_ASYNC16(st + 3 * TILE_B + so, Bl + (long)(n0 + row) * K - (long)row * K + go);
        }
    };

    // prologue: stages 0..2
    #pragma unroll
    for (int s = 0; s < 3; s++) {
        if (s < nch) load_chunk(s, s);
        CP_COMMIT();
    }

    float acc[4][4][4];
    #pragma unroll
    for (int mi = 0; mi < 4; mi++)
        #pragma unroll
        for (int nt = 0; nt < 4; nt++)
            #pragma unroll
            for (int r = 0; r < 4; r++) acc[mi][nt][r] = 0.f;

    const int ar = lane & 15;                       // A ldmatrix row-in-tile
    const int axc = lane >> 4;                      // A chunk offset (0/1)
    const int br = (lane & 7) + ((lane & 16) >> 1); // B row-in-16 (+8 for hi half)
    const int bxc = (lane >> 3) & 1;                // B chunk offset

    for (int c = 0; c < nch; ++c) {
        CP_WAIT2();
        __syncthreads();
        if (c + 3 < nch) load_chunk(c + 3, (c + 3) & (NSTAGE - 1));
        CP_COMMIT();

        const uint32_t st = sb + (c & (NSTAGE - 1)) * STAGE_B;
        const uint32_t sAh = st, sAl = st + TILE_B, sBh = st + 2 * TILE_B, sBl = st + 3 * TILE_B;

        #pragma unroll
        for (int ks = 0; ks < 2; ks++) {
            uint32_t ah[4][4], al[4][4], bh[2][4], bl[2][4];
            const int ac = 2 * ks + axc;
            const int bc = 2 * ks + bxc;
            #pragma unroll
            for (int mi = 0; mi < 4; mi++) {
                LDSM_X4(ah[mi], sAh + swz64(wm + mi * 16 + ar, ac));
                LDSM_X4(al[mi], sAl + swz64(wm + mi * 16 + ar, ac));
            }
            #pragma unroll
            for (int nj = 0; nj < 2; nj++) {
                LDSM_X4(bh[nj], sBh + swz64(wn + nj * 16 + br, bc));
                LDSM_X4(bl[nj], sBl + swz64(wn + nj * 16 + br, bc));
            }
            #pragma unroll
            for (int mi = 0; mi < 4; mi++)
                #pragma unroll
                for (int nt = 0; nt < 4; nt++) {
                    const int nj = nt >> 1, pr = (nt & 1) * 2;
                    MMA_BF16(acc[mi][nt], ah[mi], bh[nj][pr], bh[nj][pr + 1]);
                    MMA_BF16(acc[mi][nt], ah[mi], bl[nj][pr], bl[nj][pr + 1]);
                    MMA_BF16(acc[mi][nt], al[mi], bh[nj][pr], bh[nj][pr + 1]);
                }
        }
    }

    // epilogue
    const int gid = lane >> 2, tig = lane & 3;
    #pragma unroll
    for (int mi = 0; mi < 4; mi++) {
        #pragma unroll
        for (int nt = 0; nt < 4; nt++) {
            const int r0 = m0 + wm + mi * 16 + gid;
            const int cc = n0 + wn + nt * 8 + tig * 2;
            const float c0 = acc[mi][nt][0] * scale, c1 = acc[mi][nt][1] * scale;
            const float c2 = acc[mi][nt][2] * scale, c3 = acc[mi][nt][3] * scale;
            if (split_out) {
                bf16 h0, l0, h1, l1, h2, l2, h3, l3;
                split1(c0, h0, l0); split1(c1, h1, l1);
                split1(c2, h2, l2); split1(c3, h3, l3);
                bf16* Hp = Chi + (long)bz * sC;
                bf16* Lp = Clo + (long)bz * sC;
                *(uint32_t*)(Hp + (long)r0 * ldc + cc)       = pack2(h0, h1);
                *(uint32_t*)(Lp + (long)r0 * ldc + cc)       = pack2(l0, l1);
                *(uint32_t*)(Hp + (long)(r0 + 8) * ldc + cc) = pack2(h2, h3);
                *(uint32_t*)(Lp + (long)(r0 + 8) * ldc + cc) = pack2(l2, l3);
            } else {
                float* Cp = Cf + (long)bz * sC;
                float2 v0; v0.x = c0; v0.y = c1;
                float2 v1; v1.x = c2; v1.y = c3;
                *(float2*)(Cp + (long)r0 * ldc + cc)       = v0;
                *(float2*)(Cp + (long)(r0 + 8) * ldc + cc) = v1;
            }
        }
    }
}

// ---------------------------------------------------------------------------
// Causal softmax: fp32 scores -> bf16 hi/lo probabilities (zeros above diag).
// ---------------------------------------------------------------------------
__global__ __launch_bounds__(256)
void softmax_causal_split(const float* __restrict__ P, bf16* __restrict__ Ph,
                          bf16* __restrict__ Pl)
{
    const int r = blockIdx.x;
    const int s = r & (SEQ - 1);
    const float* row = P + (long)r * SEQ;
    const int tid = threadIdx.x;

    float x[8];
    float m = -INFINITY;
    #pragma unroll
    for (int i = 0; i < 8; i++) {
        const int t = tid + i * 256;
        x[i] = (t <= s) ? row[t] : -INFINITY;
        m = fmaxf(m, x[i]);
    }
    __shared__ float red[256];
    red[tid] = m; __syncthreads();
    #pragma unroll
    for (int off = 128; off > 0; off >>= 1) {
        if (tid < off) red[tid] = fmaxf(red[tid], red[tid + off]);
        __syncthreads();
    }
    m = red[0];
    __syncthreads();

    float e[8], sum = 0.f;
    #pragma unroll
    for (int i = 0; i < 8; i++) {
        const int t = tid + i * 256;
        e[i] = (t <= s) ? expf(x[i] - m) : 0.f;
        sum += e[i];
    }
    red[tid] = sum; __syncthreads();
    #pragma unroll
    for (int off = 128; off > 0; off >>= 1) {
        if (tid < off) red[tid] += red[tid + off];
        __syncthreads();
    }
    const float inv = 1.f / red[0];

    bf16* ph = Ph + (long)r * SEQ;
    bf16* pl = Pl + (long)r * SEQ;
    #pragma unroll
    for (int i = 0; i < 8; i++) {
        const int t = tid + i * 256;
        bf16 h, l; split1(e[i] * inv, h, l);
        ph[t] = h; pl[t] = l;
    }
}

// ---------------------------------------------------------------------------
// Launch sequence
// ---------------------------------------------------------------------------
extern "C" void kernel_launch(void* const* d_in, const int* in_sizes, int n_in,
                              void* d_out, int out_size)
{
    const float* query = (const float*)d_in[0];
    const float* key   = (const float*)d_in[1];
    const float* value = (const float*)d_in[2];
    const float* Wq    = (const float*)d_in[4];
    const float* Wk    = (const float*)d_in[5];
    const float* Wv    = (const float*)d_in[6];
    float* out = (float*)d_out;

    bf16 *aqh, *aql, *akh, *akl, *avh, *avl;
    bf16 *wqh, *wql, *wkh, *wkl, *wvh, *wvl;
    bf16 *qh, *ql, *kh, *kl, *vth, *vtl, *ph, *pl;
    float *vf, *pf;
    cudaGetSymbolAddress((void**)&aqh, g_aqh); cudaGetSymbolAddress((void**)&aql, g_aql);
    cudaGetSymbolAddress((void**)&akh, g_akh); cudaGetSymbolAddress((void**)&akl, g_akl);
    cudaGetSymbolAddress((void**)&avh, g_avh); cudaGetSymbolAddress((void**)&avl, g_avl);
    cudaGetSymbolAddress((void**)&wqh, g_wqh); cudaGetSymbolAddress((void**)&wql, g_wql);
    cudaGetSymbolAddress((void**)&wkh, g_wkh); cudaGetSymbolAddress((void**)&wkl, g_wkl);
    cudaGetSymbolAddress((void**)&wvh, g_wvh); cudaGetSymbolAddress((void**)&wvl, g_wvl);
    cudaGetSymbolAddress((void**)&qh,  g_qh);  cudaGetSymbolAddress((void**)&ql,  g_ql);
    cudaGetSymbolAddress((void**)&kh,  g_kh);  cudaGetSymbolAddress((void**)&kl,  g_kl);
    cudaGetSymbolAddress((void**)&vf,  g_v);
    cudaGetSymbolAddress((void**)&vth, g_vth); cudaGetSymbolAddress((void**)&vtl, g_vtl);
    cudaGetSymbolAddress((void**)&pf,  g_p);
    cudaGetSymbolAddress((void**)&ph,  g_ph);  cudaGetSymbolAddress((void**)&pl,  g_pl);

    cudaFuncSetAttribute(gemm_mma, cudaFuncAttributeMaxDynamicSharedMemorySize, G_SMEM);

    // 1) Split inputs and weights to bf16 hi/lo
    const int n4x = (int)(NSD / 4), n4w = (int)(DD / 4);
    split4_kernel<<<(n4x + 255) / 256, 256>>>((const float4*)query, (uint2*)aqh, (uint2*)aql, n4x);
    split4_kernel<<<(n4x + 255) / 256, 256>>>((const float4*)key,   (uint2*)akh, (uint2*)akl, n4x);
    split4_kernel<<<(n4x + 255) / 256, 256>>>((const float4*)value, (uint2*)avh, (uint2*)avl, n4x);
    split4_kernel<<<(n4w + 255) / 256, 256>>>((const float4*)Wq, (uint2*)wqh, (uint2*)wql, n4w);
    split4_kernel<<<(n4w + 255) / 256, 256>>>((const float4*)Wk, (uint2*)wkh, (uint2*)wkl, n4w);
    split4_kernel<<<(n4w + 255) / 256, 256>>>((const float4*)Wv, (uint2*)wvh, (uint2*)wvl, n4w);

    // 2) Projections: [8192,1024] = X @ W^T   (q,k -> split out; v -> fp32)
    const dim3 gproj(DIM / 128, (BATCH * SEQ) / 128, 1);
    gemm_mma<<<gproj, 256, G_SMEM>>>(aqh, aql, 0, wqh, wql, 0,
        nullptr, qh, ql, 0, DIM, DIM, 1.f, 0, 0, 1);
    gemm_mma<<<gproj, 256, G_SMEM>>>(akh, akl, 0, wkh, wkl, 0,
        nullptr, kh, kl, 0, DIM, DIM, 1.f, 0, 0, 1);
    gemm_mma<<<gproj, 256, G_SMEM>>>(avh, avl, 0, wvh, wvl, 0,
        vf, nullptr, nullptr, 0, DIM, DIM, 1.f, 0, 0, 0);

    // 3) Transpose + split v -> [B][D][T]
    transpose_split_kernel<<<dim3(DIM / 32, SEQ / 32, BATCH), 256>>>(vf, vth, vtl);

    // 4) Scores: P = (Q K^T)/32, lower-triangle tiles only, fp32 out
    const dim3 gqk(SEQ / 128, SEQ / 128, BATCH);
    gemm_mma<<<gqk, 256, G_SMEM>>>(qh, ql, (long)SEQ * DIM, kh, kl, (long)SEQ * DIM,
        pf, nullptr, nullptr, (long)SEQ * SEQ, DIM, SEQ, 0.03125f, 1, 0, 0);

    // 5) Causal softmax -> bf16 hi/lo probabilities
    softmax_causal_split<<<BATCH * SEQ, 256>>>(pf, ph, pl);

    // 6) Output: Y = P @ V  (NT against transposed V, k bounded by diagonal)
    const dim3 gpv(DIM / 128, SEQ / 128, BATCH);
    gemm_mma<<<gpv, 256, G_SMEM>>>(ph, pl, (long)SEQ * SEQ, vth, vtl, (long)DIM * SEQ,
        out, nullptr, nullptr, (long)SEQ * DIM, SEQ, DIM, 1.f, 0, 1, 0);
}